// round 2
// baseline (speedup 1.0000x reference)
#include <cuda_runtime.h>
#include <cstdint>

#define BATCH 32
#define NKVH 8
#define HIDDEN 4096
#define NQKV 6144
#define KSPLIT 16
#define NSPLIT 8
#define CHUNK 256
#define ATT_SCALE 0.08838834764831843f

__device__ float g_part[KSPLIT * BATCH * NQKV];
__device__ float g_q[BATCH * HIDDEN];
__device__ float g_kn[BATCH * NKVH * 128];
__device__ float g_vn[BATCH * NKVH * 128];
__device__ float g_pm[BATCH * NKVH * NSPLIT * 4];
__device__ float g_pl[BATCH * NKVH * NSPLIT * 4];
__device__ float g_pacc[BATCH * NKVH * NSPLIT * 4 * 128];
__device__ float g_attn[BATCH * HIDDEN];

__device__ __forceinline__ uint32_t f2tf(float f) {
    uint32_t u; asm("cvt.rna.tf32.f32 %0, %1;" : "=r"(u) : "f"(f)); return u;
}
__device__ __forceinline__ void mma8(float* d, const uint32_t* a, const uint32_t* b) {
    asm volatile("mma.sync.aligned.m16n8k8.row.col.f32.tf32.tf32.f32 "
        "{%0,%1,%2,%3},{%4,%5,%6,%7},{%8,%9},{%0,%1,%2,%3};"
        : "+f"(d[0]), "+f"(d[1]), "+f"(d[2]), "+f"(d[3])
        : "r"(a[0]), "r"(a[1]), "r"(a[2]), "r"(a[3]), "r"(b[0]), "r"(b[1]));
}
__device__ __forceinline__ float f4e(const float4 v, int s) {
    return s == 0 ? v.x : (s == 1 ? v.y : (s == 2 ? v.z : v.w));
}

// C[m,n] partial = sum_{k in split} A[m,k]*Bm[n,k].  M=32. grid=(N/256,KSPLIT), 256 thr.
__global__ __launch_bounds__(256) void gemm_tf32(const float* __restrict__ Ain,
                                                 const float* __restrict__ Bm,
                                                 int K, int N, int use_gattn) {
    const float* A = use_gattn ? g_attn : Ain;
    int w = threadIdx.x >> 5, lane = threadIdx.x & 31;
    int c = lane & 3, g = lane >> 2;
    int nbase = blockIdx.x * 256 + w * 32;
    int kper = K / KSPLIT, k0 = blockIdx.y * kper;

    float d[2][4][4];
#pragma unroll
    for (int t = 0; t < 2; t++)
#pragma unroll
        for (int j = 0; j < 4; j++)
#pragma unroll
            for (int q = 0; q < 4; q++) d[t][j][q] = 0.f;

    const float *Ap[4], *Bp[4];
#pragma unroll
    for (int r = 0; r < 4; r++) Ap[r] = A + (size_t)(g + 8 * r) * K + c * 8;
#pragma unroll
    for (int j = 0; j < 4; j++) Bp[j] = Bm + (size_t)(nbase + 8 * j + g) * K + c * 8;

    for (int kc = k0; kc < k0 + kper; kc += 32) {
        float4 al[4], ah[4], bl[4], bh[4];
#pragma unroll
        for (int r = 0; r < 4; r++) {
            al[r] = *(const float4*)(Ap[r] + kc);
            ah[r] = *(const float4*)(Ap[r] + kc + 4);
        }
#pragma unroll
        for (int j = 0; j < 4; j++) {
            bl[j] = *(const float4*)(Bp[j] + kc);
            bh[j] = *(const float4*)(Bp[j] + kc + 4);
        }
#pragma unroll
        for (int s = 0; s < 4; s++) {
            uint32_t bf[4][2];
#pragma unroll
            for (int j = 0; j < 4; j++) { bf[j][0] = f2tf(f4e(bl[j], s)); bf[j][1] = f2tf(f4e(bh[j], s)); }
#pragma unroll
            for (int t = 0; t < 2; t++) {
                float av[4] = { f4e(al[2*t], s), f4e(al[2*t+1], s), f4e(ah[2*t], s), f4e(ah[2*t+1], s) };
                uint32_t ahi[4], alo[4];
#pragma unroll
                for (int q = 0; q < 4; q++) {
                    ahi[q] = f2tf(av[q]);
                    alo[q] = f2tf(av[q] - __uint_as_float(ahi[q]));
                }
#pragma unroll
                for (int j = 0; j < 4; j++) { mma8(d[t][j], ahi, bf[j]); mma8(d[t][j], alo, bf[j]); }
            }
        }
    }
    float* outp = g_part + (size_t)blockIdx.y * BATCH * N;
#pragma unroll
    for (int t = 0; t < 2; t++)
#pragma unroll
        for (int j = 0; j < 4; j++) {
            int row = g + 16 * t, col = nbase + 8 * j + 2 * c;
            *(float2*)(outp + (size_t)row * N + col)       = make_float2(d[t][j][0], d[t][j][1]);
            *(float2*)(outp + (size_t)(row + 8) * N + col) = make_float2(d[t][j][2], d[t][j][3]);
        }
}

__global__ void reduce_qkv(const float* __restrict__ bias, const int* __restrict__ ctx) {
    int t = blockIdx.x * blockDim.x + threadIdx.x;
    if (t >= BATCH * NQKV) return;
    int b = t / NQKV, n = t % NQKV;
    int pos = ctx[b] - 1;
    if (n < 5120) {
        int base = (n < 4096) ? 0 : 4096;
        int loc = n - base, h = loc >> 7, dd = loc & 127;
        if (dd >= 64) return;
        float x1 = bias[n], x2 = bias[n + 64];
        for (int i = 0; i < KSPLIT; i++) {
            x1 += g_part[(size_t)i * BATCH * NQKV + b * NQKV + n];
            x2 += g_part[(size_t)i * BATCH * NQKV + b * NQKV + n + 64];
        }
        double ifr = exp(-(double)dd / 64.0 * log(10000.0));
        float ang = (float)pos * (float)ifr;
        float cs = cosf(ang), sn = sinf(ang);
        float o1 = x1 * cs - x2 * sn, o2 = x2 * cs + x1 * sn;
        if (n < 4096) {
            g_q[b * HIDDEN + h * 128 + dd]      = o1 * ATT_SCALE;
            g_q[b * HIDDEN + h * 128 + dd + 64] = o2 * ATT_SCALE;
        } else {
            g_kn[b * 1024 + h * 128 + dd]      = o1;
            g_kn[b * 1024 + h * 128 + dd + 64] = o2;
        }
    } else {
        float s = bias[n];
        for (int i = 0; i < KSPLIT; i++) s += g_part[(size_t)i * BATCH * NQKV + b * NQKV + n];
        g_vn[b * 1024 + (n - 5120)] = s;
    }
}

__global__ __launch_bounds__(128) void attn_split(const float* __restrict__ kc,
                                                  const float* __restrict__ vc,
                                                  const int* __restrict__ bt,
                                                  const int* __restrict__ ctx) {
    int split = blockIdx.x, kvh = blockIdx.y, b = blockIdx.z;
    int tid = threadIdx.x, w = tid >> 5, lane = tid & 31;
    int L = ctx[b], pos = L - 1;
    __shared__ float sq[4][128];
    __shared__ float se[4][32][4];
    __shared__ const float* svp[4][32];
    __shared__ float sm[4][4], sl[4][4];
    __shared__ float sacc[4][4][128];
    for (int i = tid; i < 512; i += 128) sq[i >> 7][i & 127] = g_q[b * HIDDEN + kvh * 512 + i];
    __syncthreads();

    float m[4] = {-1e30f, -1e30f, -1e30f, -1e30f};
    float lsum[4] = {0, 0, 0, 0};
    float acc[4][4] = {};
    int p0 = split * CHUNK + w * 64;
    for (int it = 0; it < 2; it++) {
        int p = p0 + it * 32 + lane;
        bool valid = p < L;
        float s[4] = {-1e30f, -1e30f, -1e30f, -1e30f};
        const float* vrow = vc;
        if (valid) {
            const float* krow;
            if (p == pos) { krow = g_kn + (b * 8 + kvh) * 128; vrow = g_vn + (b * 8 + kvh) * 128; }
            else {
                long long off = ((long long)(bt[b * 128 + (p >> 4)] * 16 + (p & 15)) * 8 + kvh) * 128;
                krow = kc + off; vrow = vc + off;
            }
            float t0 = 0, t1 = 0, t2 = 0, t3 = 0;
#pragma unroll
            for (int j = 0; j < 32; j++) {
                float4 k4 = ((const float4*)krow)[j];
                float4 q0 = ((const float4*)sq[0])[j], q1 = ((const float4*)sq[1])[j];
                float4 q2 = ((const float4*)sq[2])[j], q3 = ((const float4*)sq[3])[j];
                t0 += k4.x*q0.x + k4.y*q0.y + k4.z*q0.z + k4.w*q0.w;
                t1 += k4.x*q1.x + k4.y*q1.y + k4.z*q1.z + k4.w*q1.w;
                t2 += k4.x*q2.x + k4.y*q2.y + k4.z*q2.z + k4.w*q2.w;
                t3 += k4.x*q3.x + k4.y*q3.y + k4.z*q3.z + k4.w*q3.w;
            }
            s[0] = t0; s[1] = t1; s[2] = t2; s[3] = t3;
        }
        svp[w][lane] = vrow;
        float e[4];
#pragma unroll
        for (int h = 0; h < 4; h++) {
            float mx = s[h];
            for (int o = 16; o; o >>= 1) mx = fmaxf(mx, __shfl_xor_sync(~0u, mx, o));
            float mn = fmaxf(m[h], mx);
            float corr = expf(m[h] - mn);
            m[h] = mn;
            e[h] = valid ? expf(s[h] - mn) : 0.f;
            lsum[h] = lsum[h] * corr + e[h];
#pragma unroll
            for (int j = 0; j < 4; j++) acc[h][j] *= corr;
        }
        *(float4*)se[w][lane] = make_float4(e[0], e[1], e[2], e[3]);
        __syncwarp();
#pragma unroll 4
        for (int pp = 0; pp < 32; pp++) {
            float4 e4 = *(const float4*)se[w][pp];
            float4 v4 = ((const float4*)svp[w][pp])[lane];
            acc[0][0] += e4.x*v4.x; acc[0][1] += e4.x*v4.y; acc[0][2] += e4.x*v4.z; acc[0][3] += e4.x*v4.w;
            acc[1][0] += e4.y*v4.x; acc[1][1] += e4.y*v4.y; acc[1][2] += e4.y*v4.z; acc[1][3] += e4.y*v4.w;
            acc[2][0] += e4.z*v4.x; acc[2][1] += e4.z*v4.y; acc[2][2] += e4.z*v4.z; acc[2][3] += e4.z*v4.w;
            acc[3][0] += e4.w*v4.x; acc[3][1] += e4.w*v4.y; acc[3][2] += e4.w*v4.z; acc[3][3] += e4.w*v4.w;
        }
        __syncwarp();
    }
#pragma unroll
    for (int h = 0; h < 4; h++) {
        float lt = lsum[h];
        for (int o = 16; o; o >>= 1) lt += __shfl_xor_sync(~0u, lt, o);
        if (lane == 0) { sm[w][h] = m[h]; sl[w][h] = lt; }
#pragma unroll
        for (int j = 0; j < 4; j++) sacc[w][h][lane * 4 + j] = acc[h][j];
    }
    __syncthreads();
    for (int h = 0; h < 4; h++) {
        float mb = fmaxf(fmaxf(sm[0][h], sm[1][h]), fmaxf(sm[2][h], sm[3][h]));
        float lb = 0, ab = 0;
        for (int ww = 0; ww < 4; ww++) {
            float e = expf(sm[ww][h] - mb);
            lb += e * sl[ww][h];
            ab += e * sacc[ww][h][tid];
        }
        int idx = ((b * 8 + kvh) * NSPLIT + split) * 4 + h;
        if (tid == 0) { g_pm[idx] = mb; g_pl[idx] = lb; }
        g_pacc[(size_t)idx * 128 + tid] = ab;
    }
}

__global__ __launch_bounds__(128) void attn_reduce() {
    int kvh = blockIdx.x, b = blockIdx.y, t = threadIdx.x;
    for (int h = 0; h < 4; h++) {
        float mb = -1e30f;
        for (int s = 0; s < NSPLIT; s++)
            mb = fmaxf(mb, g_pm[((b * 8 + kvh) * NSPLIT + s) * 4 + h]);
        float lt = 0, a = 0;
        for (int s = 0; s < NSPLIT; s++) {
            int idx = ((b * 8 + kvh) * NSPLIT + s) * 4 + h;
            float e = expf(g_pm[idx] - mb);
            lt += e * g_pl[idx];
            a += e * g_pacc[(size_t)idx * 128 + t];
        }
        g_attn[b * HIDDEN + (kvh * 4 + h) * 128 + t] = a / lt;
    }
}

__global__ void reduce_out(const float* __restrict__ bias, float* __restrict__ out) {
    int t = blockIdx.x * blockDim.x + threadIdx.x;
    if (t >= BATCH * HIDDEN) return;
    int b = t / HIDDEN, n = t % HIDDEN;
    float s = bias[n];
    for (int i = 0; i < KSPLIT; i++) s += g_part[(size_t)i * BATCH * HIDDEN + b * HIDDEN + n];
    out[t] = s;
}

extern "C" void kernel_launch(void* const* d_in, const int* in_sizes, int n_in,
                              void* d_out, int out_size) {
    const float* hs = (const float*)d_in[0];
    const float* Wq = (const float*)d_in[1];
    const float* bq = (const float*)d_in[2];
    const float* Wo = (const float*)d_in[3];
    const float* bo = (const float*)d_in[4];
    const float* kc = (const float*)d_in[5];
    const float* vc = (const float*)d_in[6];
    const int*   bt = (const int*)d_in[7];
    const int*  ctx = (const int*)d_in[8];
    float* out = (float*)d_out;

    gemm_tf32<<<dim3(NQKV / 256, KSPLIT), 256>>>(hs, Wq, HIDDEN, NQKV, 0);
    reduce_qkv<<<(BATCH * NQKV + 255) / 256, 256>>>(bq, ctx);
    attn_split<<<dim3(NSPLIT, NKVH, BATCH), 128>>>(kc, vc, bt, ctx);
    attn_reduce<<<dim3(NKVH, BATCH), 128>>>();
    gemm_tf32<<<dim3(HIDDEN / 256, KSPLIT), 256>>>(nullptr, Wo, HIDDEN, HIDDEN, 1);
    reduce_out<<<(BATCH * HIDDEN + 255) / 256, 256>>>(bo, out);
}

// round 3
// speedup vs baseline: 1.0794x; 1.0794x over previous
#include <cuda_runtime.h>
#include <cstdint>

#define BATCH 32
#define NKVH 8
#define HIDDEN 4096
#define NQKV 6144
#define KSPLIT 16
#define NSPLIT 8
#define CHUNK 256
#define ATT_SCALE 0.08838834764831843f

__device__ float g_part[KSPLIT * BATCH * NQKV];
__device__ float g_q[BATCH * HIDDEN];
__device__ float g_kn[BATCH * NKVH * 128];
__device__ float g_vn[BATCH * NKVH * 128];
__device__ float g_pm[BATCH * NKVH * NSPLIT * 4];
__device__ float g_pl[BATCH * NKVH * NSPLIT * 4];
__device__ float g_pacc[BATCH * NKVH * NSPLIT * 4 * 128];
__device__ float g_attn[BATCH * HIDDEN];

__device__ __forceinline__ uint32_t f2tf(float f) {
    uint32_t u; asm("cvt.rna.tf32.f32 %0, %1;" : "=r"(u) : "f"(f)); return u;
}
__device__ __forceinline__ void mma8(float* d, const uint32_t* a, const uint32_t* b) {
    asm volatile("mma.sync.aligned.m16n8k8.row.col.f32.tf32.tf32.f32 "
        "{%0,%1,%2,%3},{%4,%5,%6,%7},{%8,%9},{%0,%1,%2,%3};"
        : "+f"(d[0]), "+f"(d[1]), "+f"(d[2]), "+f"(d[3])
        : "r"(a[0]), "r"(a[1]), "r"(a[2]), "r"(a[3]), "r"(b[0]), "r"(b[1]));
}
__device__ __forceinline__ float f4e(const float4 v, int s) {
    return s == 0 ? v.x : (s == 1 ? v.y : (s == 2 ? v.z : v.w));
}

// C[m,n] partial = sum_{k in split} A[m,k]*Bm[n,k].  M=32. grid=(N/256,KSPLIT), 256 thr.
__global__ __launch_bounds__(256) void gemm_tf32(const float* __restrict__ Ain,
                                                 const float* __restrict__ Bm,
                                                 int K, int N, int use_gattn) {
    const float* A = use_gattn ? g_attn : Ain;
    int w = threadIdx.x >> 5, lane = threadIdx.x & 31;
    int c = lane & 3, g = lane >> 2;
    int nbase = blockIdx.x * 256 + w * 32;
    int kper = K / KSPLIT, k0 = blockIdx.y * kper;

    float d[2][4][4];
#pragma unroll
    for (int t = 0; t < 2; t++)
#pragma unroll
        for (int j = 0; j < 4; j++)
#pragma unroll
            for (int q = 0; q < 4; q++) d[t][j][q] = 0.f;

    const float *Ap[4], *Bp[4];
#pragma unroll
    for (int r = 0; r < 4; r++) Ap[r] = A + (size_t)(g + 8 * r) * K + c * 8;
#pragma unroll
    for (int j = 0; j < 4; j++) Bp[j] = Bm + (size_t)(nbase + 8 * j + g) * K + c * 8;

    for (int kc = k0; kc < k0 + kper; kc += 32) {
        float4 al[4], ah[4], bl[4], bh[4];
#pragma unroll
        for (int r = 0; r < 4; r++) {
            al[r] = *(const float4*)(Ap[r] + kc);
            ah[r] = *(const float4*)(Ap[r] + kc + 4);
        }
#pragma unroll
        for (int j = 0; j < 4; j++) {
            bl[j] = *(const float4*)(Bp[j] + kc);
            bh[j] = *(const float4*)(Bp[j] + kc + 4);
        }
#pragma unroll
        for (int s = 0; s < 4; s++) {
            uint32_t bf[4][2];
#pragma unroll
            for (int j = 0; j < 4; j++) { bf[j][0] = f2tf(f4e(bl[j], s)); bf[j][1] = f2tf(f4e(bh[j], s)); }
#pragma unroll
            for (int t = 0; t < 2; t++) {
                float av[4] = { f4e(al[2*t], s), f4e(al[2*t+1], s), f4e(ah[2*t], s), f4e(ah[2*t+1], s) };
                uint32_t ahi[4], alo[4];
#pragma unroll
                for (int q = 0; q < 4; q++) {
                    ahi[q] = f2tf(av[q]);
                    alo[q] = f2tf(av[q] - __uint_as_float(ahi[q]));
                }
#pragma unroll
                for (int j = 0; j < 4; j++) { mma8(d[t][j], ahi, bf[j]); mma8(d[t][j], alo, bf[j]); }
            }
        }
    }
    float* outp = g_part + (size_t)blockIdx.y * BATCH * N;
#pragma unroll
    for (int t = 0; t < 2; t++)
#pragma unroll
        for (int j = 0; j < 4; j++) {
            int row = g + 16 * t, col = nbase + 8 * j + 2 * c;
            *(float2*)(outp + (size_t)row * N + col)       = make_float2(d[t][j][0], d[t][j][1]);
            *(float2*)(outp + (size_t)(row + 8) * N + col) = make_float2(d[t][j][2], d[t][j][3]);
        }
}

__global__ void reduce_qkv(const float* __restrict__ bias, const int* __restrict__ ctx) {
    int t = blockIdx.x * blockDim.x + threadIdx.x;
    if (t >= BATCH * NQKV) return;
    int b = t / NQKV, n = t % NQKV;
    int pos = ctx[b] - 1;
    if (n < 5120) {
        int base = (n < 4096) ? 0 : 4096;
        int loc = n - base, h = loc >> 7, dd = loc & 127;
        if (dd >= 64) return;
        float x1 = bias[n], x2 = bias[n + 64];
        for (int i = 0; i < KSPLIT; i++) {
            x1 += g_part[(size_t)i * BATCH * NQKV + b * NQKV + n];
            x2 += g_part[(size_t)i * BATCH * NQKV + b * NQKV + n + 64];
        }
        double ifr = exp(-(double)dd / 64.0 * log(10000.0));
        float ang = (float)pos * (float)ifr;
        float cs = cosf(ang), sn = sinf(ang);
        float o1 = x1 * cs - x2 * sn, o2 = x2 * cs + x1 * sn;
        if (n < 4096) {
            g_q[b * HIDDEN + h * 128 + dd]      = o1 * ATT_SCALE;
            g_q[b * HIDDEN + h * 128 + dd + 64] = o2 * ATT_SCALE;
        } else {
            g_kn[b * 1024 + h * 128 + dd]      = o1;
            g_kn[b * 1024 + h * 128 + dd + 64] = o2;
        }
    } else {
        float s = bias[n];
        for (int i = 0; i < KSPLIT; i++) s += g_part[(size_t)i * BATCH * NQKV + b * NQKV + n];
        g_vn[b * 1024 + (n - 5120)] = s;
    }
}

__global__ __launch_bounds__(128) void attn_split(const float* __restrict__ kc,
                                                  const float* __restrict__ vc,
                                                  const int* __restrict__ bt,
                                                  const int* __restrict__ ctx) {
    int split = blockIdx.x, kvh = blockIdx.y, b = blockIdx.z;
    int L = ctx[b];
    if (split * CHUNK >= L) return;  // dead split: attn_reduce skips it too
    int tid = threadIdx.x, w = tid >> 5, lane = tid & 31;
    int pos = L - 1;
    __shared__ float sq[4][128];
    __shared__ float se[4][32][4];
    __shared__ const float* svp[4][32];
    __shared__ float sm[4][4], sl[4][4];
    __shared__ float sacc[4][4][128];
    for (int i = tid; i < 512; i += 128) sq[i >> 7][i & 127] = g_q[b * HIDDEN + kvh * 512 + i];
    __syncthreads();

    float m[4] = {-1e30f, -1e30f, -1e30f, -1e30f};
    float lsum[4] = {0, 0, 0, 0};
    float acc[4][4] = {};
    int p0 = split * CHUNK + w * 64;
    for (int it = 0; it < 2; it++) {
        int base = p0 + it * 32;
        int nv = L - base;                // valid prefix length in this warp-iter
        if (nv <= 0) continue;            // warp-uniform
        if (nv > 32) nv = 32;
        int p = base + lane;
        bool valid = lane < nv;
        float s[4] = {-1e30f, -1e30f, -1e30f, -1e30f};
        const float* vrow = vc;
        if (valid) {
            const float* krow;
            if (p == pos) { krow = g_kn + (b * 8 + kvh) * 128; vrow = g_vn + (b * 8 + kvh) * 128; }
            else {
                long long off = ((long long)(bt[b * 128 + (p >> 4)] * 16 + (p & 15)) * 8 + kvh) * 128;
                krow = kc + off; vrow = vc + off;
            }
            float t0 = 0, t1 = 0, t2 = 0, t3 = 0;
#pragma unroll
            for (int j = 0; j < 32; j++) {
                float4 k4 = ((const float4*)krow)[j];
                float4 q0 = ((const float4*)sq[0])[j], q1 = ((const float4*)sq[1])[j];
                float4 q2 = ((const float4*)sq[2])[j], q3 = ((const float4*)sq[3])[j];
                t0 += k4.x*q0.x + k4.y*q0.y + k4.z*q0.z + k4.w*q0.w;
                t1 += k4.x*q1.x + k4.y*q1.y + k4.z*q1.z + k4.w*q1.w;
                t2 += k4.x*q2.x + k4.y*q2.y + k4.z*q2.z + k4.w*q2.w;
                t3 += k4.x*q3.x + k4.y*q3.y + k4.z*q3.z + k4.w*q3.w;
            }
            s[0] = t0; s[1] = t1; s[2] = t2; s[3] = t3;
        }
        svp[w][lane] = vrow;
        float e[4];
#pragma unroll
        for (int h = 0; h < 4; h++) {
            float mx = s[h];
            for (int o = 16; o; o >>= 1) mx = fmaxf(mx, __shfl_xor_sync(~0u, mx, o));
            float mn = fmaxf(m[h], mx);
            float corr = expf(m[h] - mn);
            m[h] = mn;
            e[h] = valid ? expf(s[h] - mn) : 0.f;
            lsum[h] = lsum[h] * corr + e[h];
#pragma unroll
            for (int j = 0; j < 4; j++) acc[h][j] *= corr;
        }
        *(float4*)se[w][lane] = make_float4(e[0], e[1], e[2], e[3]);
        __syncwarp();
        for (int pp = 0; pp < nv; pp++) {   // only valid prefix: no dead V traffic
            float4 e4 = *(const float4*)se[w][pp];
            float4 v4 = ((const float4*)svp[w][pp])[lane];
            acc[0][0] += e4.x*v4.x; acc[0][1] += e4.x*v4.y; acc[0][2] += e4.x*v4.z; acc[0][3] += e4.x*v4.w;
            acc[1][0] += e4.y*v4.x; acc[1][1] += e4.y*v4.y; acc[1][2] += e4.y*v4.z; acc[1][3] += e4.y*v4.w;
            acc[2][0] += e4.z*v4.x; acc[2][1] += e4.z*v4.y; acc[2][2] += e4.z*v4.z; acc[2][3] += e4.z*v4.w;
            acc[3][0] += e4.w*v4.x; acc[3][1] += e4.w*v4.y; acc[3][2] += e4.w*v4.z; acc[3][3] += e4.w*v4.w;
        }
        __syncwarp();
    }
#pragma unroll
    for (int h = 0; h < 4; h++) {
        float lt = lsum[h];
        for (int o = 16; o; o >>= 1) lt += __shfl_xor_sync(~0u, lt, o);
        if (lane == 0) { sm[w][h] = m[h]; sl[w][h] = lt; }
#pragma unroll
        for (int j = 0; j < 4; j++) sacc[w][h][lane * 4 + j] = acc[h][j];
    }
    __syncthreads();
    for (int h = 0; h < 4; h++) {
        float mb = fmaxf(fmaxf(sm[0][h], sm[1][h]), fmaxf(sm[2][h], sm[3][h]));
        float lb = 0, ab = 0;
        for (int ww = 0; ww < 4; ww++) {
            float e = expf(sm[ww][h] - mb);
            lb += e * sl[ww][h];
            ab += e * sacc[ww][h][tid];
        }
        int idx = ((b * 8 + kvh) * NSPLIT + split) * 4 + h;
        if (tid == 0) { g_pm[idx] = mb; g_pl[idx] = lb; }
        g_pacc[(size_t)idx * 128 + tid] = ab;
    }
}

// grid (NKVH*4, BATCH), 128 threads: one thread per output d element.
__global__ __launch_bounds__(128) void attn_reduce(const int* __restrict__ ctx) {
    int kvh = blockIdx.x >> 2, h = blockIdx.x & 3, b = blockIdx.y, t = threadIdx.x;
    int L = ctx[b];
    int nact = (L + CHUNK - 1) / CHUNK;
    if (nact > NSPLIT) nact = NSPLIT;
    int base = ((b * 8 + kvh) * NSPLIT) * 4 + h;
    float mb = -1e30f;
    for (int s = 0; s < nact; s++) mb = fmaxf(mb, g_pm[base + s * 4]);
    float lt = 0.f, a = 0.f;
    for (int s = 0; s < nact; s++) {
        int idx = base + s * 4;
        float e = expf(g_pm[idx] - mb);
        lt += e * g_pl[idx];
        a += e * g_pacc[(size_t)idx * 128 + t];
    }
    g_attn[b * HIDDEN + (kvh * 4 + h) * 128 + t] = a / lt;
}

__global__ void reduce_out(const float* __restrict__ bias, float* __restrict__ out) {
    int t = blockIdx.x * blockDim.x + threadIdx.x;
    if (t >= BATCH * HIDDEN) return;
    int b = t / HIDDEN, n = t % HIDDEN;
    float s = bias[n];
    for (int i = 0; i < KSPLIT; i++) s += g_part[(size_t)i * BATCH * HIDDEN + b * HIDDEN + n];
    out[t] = s;
}

extern "C" void kernel_launch(void* const* d_in, const int* in_sizes, int n_in,
                              void* d_out, int out_size) {
    const float* hs = (const float*)d_in[0];
    const float* Wq = (const float*)d_in[1];
    const float* bq = (const float*)d_in[2];
    const float* Wo = (const float*)d_in[3];
    const float* bo = (const float*)d_in[4];
    const float* kc = (const float*)d_in[5];
    const float* vc = (const float*)d_in[6];
    const int*   bt = (const int*)d_in[7];
    const int*  ctx = (const int*)d_in[8];
    float* out = (float*)d_out;

    gemm_tf32<<<dim3(NQKV / 256, KSPLIT), 256>>>(hs, Wq, HIDDEN, NQKV, 0);
    reduce_qkv<<<(BATCH * NQKV + 255) / 256, 256>>>(bq, ctx);
    attn_split<<<dim3(NSPLIT, NKVH, BATCH), 128>>>(kc, vc, bt, ctx);
    attn_reduce<<<dim3(NKVH * 4, BATCH), 128>>>(ctx);
    gemm_tf32<<<dim3(HIDDEN / 256, KSPLIT), 256>>>(nullptr, Wo, HIDDEN, HIDDEN, 1);
    reduce_out<<<(BATCH * HIDDEN + 255) / 256, 256>>>(bo, out);
}

// round 4
// speedup vs baseline: 1.1072x; 1.0257x over previous
#include <cuda_runtime.h>
#include <cstdint>

#define BATCH 32
#define NKVH 8
#define HIDDEN 4096
#define NQKV 6144
#define KSPLIT 16
#define NSPLIT 8
#define CHUNK 256
#define ATT_SCALE 0.08838834764831843f

__device__ float g_part[KSPLIT * BATCH * NQKV];
__device__ float g_Ahi[BATCH * HIDDEN];
__device__ float g_Alo[BATCH * HIDDEN];
__device__ float g_q[BATCH * HIDDEN];
__device__ float g_kn[BATCH * NKVH * 128];
__device__ float g_vn[BATCH * NKVH * 128];
__device__ float g_pm[BATCH * NKVH * NSPLIT * 4];
__device__ float g_pl[BATCH * NKVH * NSPLIT * 4];
__device__ float g_pacc[BATCH * NKVH * NSPLIT * 4 * 128];

__device__ __forceinline__ uint32_t f2tf(float f) {
    uint32_t u; asm("cvt.rna.tf32.f32 %0, %1;" : "=r"(u) : "f"(f)); return u;
}
__device__ __forceinline__ void mma8(float* d, const uint32_t* a, const uint32_t* b) {
    asm volatile("mma.sync.aligned.m16n8k8.row.col.f32.tf32.tf32.f32 "
        "{%0,%1,%2,%3},{%4,%5,%6,%7},{%8,%9},{%0,%1,%2,%3};"
        : "+f"(d[0]), "+f"(d[1]), "+f"(d[2]), "+f"(d[3])
        : "r"(a[0]), "r"(a[1]), "r"(a[2]), "r"(a[3]), "r"(b[0]), "r"(b[1]));
}
__device__ __forceinline__ float f4e(const float4 v, int s) {
    return s == 0 ? v.x : (s == 1 ? v.y : (s == 2 ? v.z : v.w));
}
__device__ __forceinline__ uint32_t f4u(const float4 v, int s) {
    return __float_as_uint(f4e(v, s));
}

// Split A (32 x 4096 fp32) into tf32 hi/lo once.
__global__ void split_a(const float* __restrict__ A) {
    int t = blockIdx.x * blockDim.x + threadIdx.x;
    if (t >= BATCH * HIDDEN) return;
    float x = A[t];
    uint32_t hi = f2tf(x);
    g_Ahi[t] = __uint_as_float(hi);
    g_Alo[t] = __uint_as_float(f2tf(x - __uint_as_float(hi)));
}

// C[m,n] partial = sum_{k in split} A[m,k]*Bm[n,k].  A preconverted (g_Ahi/g_Alo).
// M=32, K=4096. grid=(N/256, KSPLIT), 256 thr. Per-warp tile 32x32.
__global__ __launch_bounds__(256) void gemm_tf32(const float* __restrict__ Bm, int N) {
    int w = threadIdx.x >> 5, lane = threadIdx.x & 31;
    int c = lane & 3, g = lane >> 2;
    int nbase = blockIdx.x * 256 + w * 32;
    const int kper = HIDDEN / KSPLIT;
    int k0 = blockIdx.y * kper;

    float d[2][4][4];
#pragma unroll
    for (int t = 0; t < 2; t++)
#pragma unroll
        for (int j = 0; j < 4; j++)
#pragma unroll
            for (int q = 0; q < 4; q++) d[t][j][q] = 0.f;

    const float *AH[4], *AL[4], *Bp[4];
#pragma unroll
    for (int r = 0; r < 4; r++) {
        AH[r] = g_Ahi + (size_t)(g + 8 * r) * HIDDEN + c * 8;
        AL[r] = g_Alo + (size_t)(g + 8 * r) * HIDDEN + c * 8;
    }
#pragma unroll
    for (int j = 0; j < 4; j++) Bp[j] = Bm + (size_t)(nbase + 8 * j + g) * HIDDEN + c * 8;

    for (int kc = k0; kc < k0 + kper; kc += 32) {
        float4 bl[4], bh[4];
#pragma unroll
        for (int j = 0; j < 4; j++) {
            bl[j] = *(const float4*)(Bp[j] + kc);
            bh[j] = *(const float4*)(Bp[j] + kc + 4);
        }
        uint32_t bf[4][4][2];
#pragma unroll
        for (int s = 0; s < 4; s++)
#pragma unroll
            for (int j = 0; j < 4; j++) {
                bf[s][j][0] = f2tf(f4e(bl[j], s));
                bf[s][j][1] = f2tf(f4e(bh[j], s));
            }
        float4 x0[4], x1[4];
#pragma unroll
        for (int r = 0; r < 4; r++) {
            x0[r] = *(const float4*)(AH[r] + kc);
            x1[r] = *(const float4*)(AH[r] + kc + 4);
        }
#pragma unroll
        for (int s = 0; s < 4; s++)
#pragma unroll
            for (int t = 0; t < 2; t++) {
                uint32_t af[4] = { f4u(x0[2*t], s), f4u(x0[2*t+1], s), f4u(x1[2*t], s), f4u(x1[2*t+1], s) };
#pragma unroll
                for (int j = 0; j < 4; j++) mma8(d[t][j], af, bf[s][j]);
            }
#pragma unroll
        for (int r = 0; r < 4; r++) {
            x0[r] = *(const float4*)(AL[r] + kc);
            x1[r] = *(const float4*)(AL[r] + kc + 4);
        }
#pragma unroll
        for (int s = 0; s < 4; s++)
#pragma unroll
            for (int t = 0; t < 2; t++) {
                uint32_t af[4] = { f4u(x0[2*t], s), f4u(x0[2*t+1], s), f4u(x1[2*t], s), f4u(x1[2*t+1], s) };
#pragma unroll
                for (int j = 0; j < 4; j++) mma8(d[t][j], af, bf[s][j]);
            }
    }
    float* outp = g_part + (size_t)blockIdx.y * BATCH * N;
#pragma unroll
    for (int t = 0; t < 2; t++)
#pragma unroll
        for (int j = 0; j < 4; j++) {
            int row = g + 16 * t, col = nbase + 8 * j + 2 * c;
            *(float2*)(outp + (size_t)row * N + col)       = make_float2(d[t][j][0], d[t][j][1]);
            *(float2*)(outp + (size_t)(row + 8) * N + col) = make_float2(d[t][j][2], d[t][j][3]);
        }
}

__global__ void reduce_qkv(const float* __restrict__ bias, const int* __restrict__ ctx) {
    int t = blockIdx.x * blockDim.x + threadIdx.x;
    if (t >= BATCH * NQKV) return;
    int b = t / NQKV, n = t % NQKV;
    int pos = ctx[b] - 1;
    if (n < 5120) {
        int base = (n < 4096) ? 0 : 4096;
        int loc = n - base, h = loc >> 7, dd = loc & 127;
        if (dd >= 64) return;
        float x1 = bias[n], x2 = bias[n + 64];
        for (int i = 0; i < KSPLIT; i++) {
            x1 += g_part[(size_t)i * BATCH * NQKV + b * NQKV + n];
            x2 += g_part[(size_t)i * BATCH * NQKV + b * NQKV + n + 64];
        }
        double ifr = exp(-(double)dd / 64.0 * log(10000.0));
        float ang = (float)pos * (float)ifr;
        float cs = cosf(ang), sn = sinf(ang);
        float o1 = x1 * cs - x2 * sn, o2 = x2 * cs + x1 * sn;
        if (n < 4096) {
            g_q[b * HIDDEN + h * 128 + dd]      = o1 * ATT_SCALE;
            g_q[b * HIDDEN + h * 128 + dd + 64] = o2 * ATT_SCALE;
        } else {
            g_kn[b * 1024 + h * 128 + dd]      = o1;
            g_kn[b * 1024 + h * 128 + dd + 64] = o2;
        }
    } else {
        float s = bias[n];
        for (int i = 0; i < KSPLIT; i++) s += g_part[(size_t)i * BATCH * NQKV + b * NQKV + n];
        g_vn[b * 1024 + (n - 5120)] = s;
    }
}

__global__ __launch_bounds__(128) void attn_split(const float* __restrict__ kc,
                                                  const float* __restrict__ vc,
                                                  const int* __restrict__ bt,
                                                  const int* __restrict__ ctx) {
    int split = blockIdx.x, kvh = blockIdx.y, b = blockIdx.z;
    int L = ctx[b];
    if (split * CHUNK >= L) return;
    int tid = threadIdx.x, w = tid >> 5, lane = tid & 31;
    int pos = L - 1;
    __shared__ float sq[4][128];
    __shared__ float se[4][32][4];
    __shared__ const float* svp[4][32];
    __shared__ float sm[4][4], sl[4][4];
    __shared__ float sacc[4][4][128];
    for (int i = tid; i < 512; i += 128) sq[i >> 7][i & 127] = g_q[b * HIDDEN + kvh * 512 + i];
    __syncthreads();

    float m[4] = {-1e30f, -1e30f, -1e30f, -1e30f};
    float lsum[4] = {0, 0, 0, 0};
    float acc[4][4] = {};
    int p0 = split * CHUNK + w * 64;
    for (int it = 0; it < 2; it++) {
        int base = p0 + it * 32;
        int nv = L - base;
        if (nv <= 0) continue;
        if (nv > 32) nv = 32;
        int p = base + lane;
        bool valid = lane < nv;
        float s[4] = {-1e30f, -1e30f, -1e30f, -1e30f};
        const float* vrow = vc;
        if (valid) {
            const float* krow;
            if (p == pos) { krow = g_kn + (b * 8 + kvh) * 128; vrow = g_vn + (b * 8 + kvh) * 128; }
            else {
                long long off = ((long long)(bt[b * 128 + (p >> 4)] * 16 + (p & 15)) * 8 + kvh) * 128;
                krow = kc + off; vrow = vc + off;
            }
            float t0 = 0, t1 = 0, t2 = 0, t3 = 0;
#pragma unroll
            for (int j = 0; j < 32; j++) {
                float4 k4 = __ldcs((const float4*)krow + j);
                float4 q0 = ((const float4*)sq[0])[j], q1 = ((const float4*)sq[1])[j];
                float4 q2 = ((const float4*)sq[2])[j], q3 = ((const float4*)sq[3])[j];
                t0 += k4.x*q0.x + k4.y*q0.y + k4.z*q0.z + k4.w*q0.w;
                t1 += k4.x*q1.x + k4.y*q1.y + k4.z*q1.z + k4.w*q1.w;
                t2 += k4.x*q2.x + k4.y*q2.y + k4.z*q2.z + k4.w*q2.w;
                t3 += k4.x*q3.x + k4.y*q3.y + k4.z*q3.z + k4.w*q3.w;
            }
            s[0] = t0; s[1] = t1; s[2] = t2; s[3] = t3;
        }
        svp[w][lane] = vrow;
        float e[4];
#pragma unroll
        for (int h = 0; h < 4; h++) {
            float mx = s[h];
            for (int o = 16; o; o >>= 1) mx = fmaxf(mx, __shfl_xor_sync(~0u, mx, o));
            float mn = fmaxf(m[h], mx);
            float corr = expf(m[h] - mn);
            m[h] = mn;
            e[h] = valid ? expf(s[h] - mn) : 0.f;
            lsum[h] = lsum[h] * corr + e[h];
#pragma unroll
            for (int j = 0; j < 4; j++) acc[h][j] *= corr;
        }
        *(float4*)se[w][lane] = make_float4(e[0], e[1], e[2], e[3]);
        __syncwarp();
        for (int pp = 0; pp < nv; pp++) {
            float4 e4 = *(const float4*)se[w][pp];
            float4 v4 = __ldcs((const float4*)svp[w][pp] + lane);
            acc[0][0] += e4.x*v4.x; acc[0][1] += e4.x*v4.y; acc[0][2] += e4.x*v4.z; acc[0][3] += e4.x*v4.w;
            acc[1][0] += e4.y*v4.x; acc[1][1] += e4.y*v4.y; acc[1][2] += e4.y*v4.z; acc[1][3] += e4.y*v4.w;
            acc[2][0] += e4.z*v4.x; acc[2][1] += e4.z*v4.y; acc[2][2] += e4.z*v4.z; acc[2][3] += e4.z*v4.w;
            acc[3][0] += e4.w*v4.x; acc[3][1] += e4.w*v4.y; acc[3][2] += e4.w*v4.z; acc[3][3] += e4.w*v4.w;
        }
        __syncwarp();
    }
#pragma unroll
    for (int h = 0; h < 4; h++) {
        float lt = lsum[h];
        for (int o = 16; o; o >>= 1) lt += __shfl_xor_sync(~0u, lt, o);
        if (lane == 0) { sm[w][h] = m[h]; sl[w][h] = lt; }
#pragma unroll
        for (int j = 0; j < 4; j++) sacc[w][h][lane * 4 + j] = acc[h][j];
    }
    __syncthreads();
    for (int h = 0; h < 4; h++) {
        float mb = fmaxf(fmaxf(sm[0][h], sm[1][h]), fmaxf(sm[2][h], sm[3][h]));
        float lb = 0, ab = 0;
        for (int ww = 0; ww < 4; ww++) {
            float e = expf(sm[ww][h] - mb);
            lb += e * sl[ww][h];
            ab += e * sacc[ww][h][tid];
        }
        int idx = ((b * 8 + kvh) * NSPLIT + split) * 4 + h;
        if (tid == 0) { g_pm[idx] = mb; g_pl[idx] = lb; }
        g_pacc[(size_t)idx * 128 + tid] = ab;
    }
}

// grid (NKVH, BATCH), 512 threads: thread = (h, d). Writes tf32-split attn output
// directly into g_Ahi/g_Alo as the next GEMM's A.
__global__ __launch_bounds__(512) void attn_reduce(const int* __restrict__ ctx) {
    int kvh = blockIdx.x, b = blockIdx.y;
    int h = threadIdx.x >> 7, t = threadIdx.x & 127;
    int L = ctx[b];
    int nact = (L + CHUNK - 1) / CHUNK;
    if (nact > NSPLIT) nact = NSPLIT;
    int base = ((b * 8 + kvh) * NSPLIT) * 4 + h;
    float mb = -1e30f;
    for (int s = 0; s < nact; s++) mb = fmaxf(mb, g_pm[base + s * 4]);
    float lt = 0.f, a = 0.f;
    for (int s = 0; s < nact; s++) {
        int idx = base + s * 4;
        float e = expf(g_pm[idx] - mb);
        lt += e * g_pl[idx];
        a += e * g_pacc[(size_t)idx * 128 + t];
    }
    float r = a / lt;
    uint32_t hi = f2tf(r);
    int idx = b * HIDDEN + (kvh * 4 + h) * 128 + t;
    g_Ahi[idx] = __uint_as_float(hi);
    g_Alo[idx] = __uint_as_float(f2tf(r - __uint_as_float(hi)));
}

__global__ void reduce_out(const float* __restrict__ bias, float* __restrict__ out) {
    int t = blockIdx.x * blockDim.x + threadIdx.x;
    if (t >= BATCH * HIDDEN) return;
    int b = t / HIDDEN, n = t % HIDDEN;
    float s = bias[n];
    for (int i = 0; i < KSPLIT; i++) s += g_part[(size_t)i * BATCH * HIDDEN + b * HIDDEN + n];
    out[t] = s;
}

extern "C" void kernel_launch(void* const* d_in, const int* in_sizes, int n_in,
                              void* d_out, int out_size) {
    const float* hs = (const float*)d_in[0];
    const float* Wq = (const float*)d_in[1];
    const float* bq = (const float*)d_in[2];
    const float* Wo = (const float*)d_in[3];
    const float* bo = (const float*)d_in[4];
    const float* kc = (const float*)d_in[5];
    const float* vc = (const float*)d_in[6];
    const int*   bt = (const int*)d_in[7];
    const int*  ctx = (const int*)d_in[8];
    float* out = (float*)d_out;

    split_a<<<(BATCH * HIDDEN + 255) / 256, 256>>>(hs);
    gemm_tf32<<<dim3(NQKV / 256, KSPLIT), 256>>>(Wq, NQKV);
    reduce_qkv<<<(BATCH * NQKV + 255) / 256, 256>>>(bq, ctx);
    attn_split<<<dim3(NSPLIT, NKVH, BATCH), 128>>>(kc, vc, bt, ctx);
    attn_reduce<<<dim3(NKVH, BATCH), 512>>>(ctx);
    gemm_tf32<<<dim3(HIDDEN / 256, KSPLIT), 256>>>(Wo, HIDDEN);
    reduce_out<<<(BATCH * HIDDEN + 255) / 256, 256>>>(bo, out);
}